// round 10
// baseline (speedup 1.0000x reference)
#include <cuda_runtime.h>
#include <cstdint>

#define BATCH 2048
#define TLEN  4096
#define ALPHA_C 0.95f
#define THETA_C 0.05f

// scan geometry
#define ROWS_PB 64
#define SEG     256
#define NSEG    (TLEN / SEG)        // 16
#define WU      384                 // warm-up steps (alpha^384 ~ 3e-9)
#define TILE    32
#define TSTRIDE 36                  // 144B row stride; conflict-free LDS.128

#define CP_ASYNC16(dst, src) \
    asm volatile("cp.async.cg.shared.global [%0], [%1], 16;" :: "r"(dst), "l"(src))
#define CP_COMMIT() asm volatile("cp.async.commit_group;")

__device__ __forceinline__ uint32_t smem_u32(const void* p) {
    return (uint32_t)__cvta_generic_to_shared(p);
}

// ---------------------------------------------------------------------------
// Kernel 1: causal convs — bitwise-identical math (rounds 4-8), t-sliced.
// ---------------------------------------------------------------------------
__global__ void __launch_bounds__(256) conv_kernel(
    const float* __restrict__ x,
    const float* __restrict__ w8,
    const float* __restrict__ w16,
    const float* __restrict__ w32,
    float* __restrict__ u,
    int tbase)
{
    __shared__ float xs[32][97];
    __shared__ float sw8[8], sw16[16], sw32[32];

    const int tx  = threadIdx.x;
    const int ty  = threadIdx.y;
    const int tid = ty * 8 + tx;
    const int t0  = tbase + blockIdx.x * 64;
    const int b0  = blockIdx.y * 32;
    const int warp = tid >> 5;
    const int lane = tid & 31;

    if (tid < 8)       sw8[tid]       = w8[tid];
    else if (tid < 24) sw16[tid - 8]  = w16[tid - 8];
    else if (tid < 56) sw32[tid - 24] = w32[tid - 24];

    {
        const int r0 = warp << 2;
#pragma unroll
        for (int rr = 0; rr < 4; rr++) {
            const float* xrow = x + (size_t)(b0 + r0 + rr) * TLEN;
#pragma unroll
            for (int seg = 0; seg < 3; seg++) {
                int i = (seg << 5) + lane;
                int t = t0 - 32 + i;
                xs[r0 + rr][i] = (t >= 0) ? xrow[t] : 0.0f;
            }
        }
    }
    __syncthreads();

    float xw[39];
#pragma unroll
    for (int j = 0; j < 39; j++) xw[j] = xs[ty][(tx << 3) + 1 + j];

    float a8[8], a16[8], a32[8];
#pragma unroll
    for (int i = 0; i < 8; i++) { a8[i] = 0.f; a16[i] = 0.f; a32[i] = 0.f; }

#pragma unroll
    for (int j = 0; j < 32; j++) {
        float w = sw32[j];
#pragma unroll
        for (int i = 0; i < 8; i++) a32[i] = fmaf(w, xw[i + j], a32[i]);
    }
#pragma unroll
    for (int j = 0; j < 16; j++) {
        float w = sw16[j];
#pragma unroll
        for (int i = 0; i < 8; i++) a16[i] = fmaf(w, xw[16 + i + j], a16[i]);
    }
#pragma unroll
    for (int j = 0; j < 8; j++) {
        float w = sw8[j];
#pragma unroll
        for (int i = 0; i < 8; i++) a8[i] = fmaf(w, xw[24 + i + j], a8[i]);
    }

    float* ub = u + ((size_t)(b0 + ty) * 3) * TLEN + t0 + (tx << 3);
    reinterpret_cast<float4*>(ub + 0 * TLEN)[0] = make_float4(a8[0],  a8[1],  a8[2],  a8[3]);
    reinterpret_cast<float4*>(ub + 0 * TLEN)[1] = make_float4(a8[4],  a8[5],  a8[6],  a8[7]);
    reinterpret_cast<float4*>(ub + 1 * TLEN)[0] = make_float4(a16[0], a16[1], a16[2], a16[3]);
    reinterpret_cast<float4*>(ub + 1 * TLEN)[1] = make_float4(a16[4], a16[5], a16[6], a16[7]);
    reinterpret_cast<float4*>(ub + 2 * TLEN)[0] = make_float4(a32[0], a32[1], a32[2], a32[3]);
    reinterpret_cast<float4*>(ub + 2 * TLEN)[1] = make_float4(a32[4], a32[5], a32[6], a32[7]);
}

// ---------------------------------------------------------------------------
// LIF + WTA step — decision logic IDENTICAL to validated rounds 1-9.
// ---------------------------------------------------------------------------
__device__ __forceinline__ void lif_step_s(float u0, float u1, float u2,
                                           float& v0, float& v1, float& v2,
                                           float& s0, float& s1, float& s2)
{
    float w0 = fmaf(ALPHA_C, v0, u0);
    float w1 = fmaf(ALPHA_C, v1, u1);
    float w2 = fmaf(ALPHA_C, v2, u2);
    float m0 = w0 - THETA_C;
    float m1 = w1 - THETA_C;
    float m2 = w2 - THETA_C;
    float best = fmaxf(m0, fmaxf(m1, m2));
    bool fire = (best >= 0.0f);
    bool t0 = (m0 == best);
    bool t1 = (m1 == best);
    bool e0 = fire && t0;
    bool e1 = fire && t1 && !t0;
    bool e2 = fire && !t0 && !t1;
    s0 = e0 ? 1.0f : 0.0f;
    s1 = e1 ? 1.0f : 0.0f;
    s2 = e2 ? 1.0f : 0.0f;
    v0 = e0 ? m0 : w0;
    v1 = e1 ? m1 : w1;
    v2 = e2 ? m2 : w2;
}

// ---------------------------------------------------------------------------
// Kernel 2: fused LIF scan. 128 threads: 0-63 compute one row each; all 128
// stage (cp.async) + store out (issue spread over all 4 SMSPs).
// blockIdx.y = segment within this launch's group (seg_base + by).
// ---------------------------------------------------------------------------
__global__ void __launch_bounds__(128, 4) scan_fused(
    const float* __restrict__ u, float* __restrict__ s, int seg_base)
{
    __shared__ float buf[2][3][ROWS_PB][TSTRIDE];

    const int tid = threadIdx.x;              // 0..127
    const int b0  = blockIdx.x * ROWS_PB;
    const int seg = seg_base + blockIdx.y;

    const int t_out0   = seg * SEG;
    const int t_begin  = (t_out0 >= WU) ? (t_out0 - WU) : 0;
    const int ntiles   = (t_out0 + SEG - t_begin) / TILE;
    const int wu_tiles = (t_out0 - t_begin) / TILE;

    // staging: 3*64*8 = 1536 16B tasks per tile, 12 per thread
    // p = tid + 128*i -> k = p>>9, row = (p>>3)&63, f4 = p&7
    {
        int tt = t_begin;
#pragma unroll
        for (int i = 0; i < 12; i++) {
            int p = tid + (i << 7);
            int k = p >> 9, row = (p >> 3) & 63, f4 = p & 7;
            uint32_t dst = smem_u32(&buf[0][k][row][f4 << 2]);
            const float* src = u + ((size_t)(b0 + row) * 3 + k) * TLEN + tt + (f4 << 2);
            CP_ASYNC16(dst, src);
        }
        CP_COMMIT();
    }

    float v0 = 0.f, v1 = 0.f, v2 = 0.f;

#pragma unroll 1
    for (int ti = 0; ti < ntiles; ti++) {
        const int cur = ti & 1;
        const bool has_next = (ti + 1 < ntiles);
        const bool emit = (ti >= wu_tiles);

        if (has_next) {
            int tt = t_begin + (ti + 1) * TILE;
#pragma unroll
            for (int i = 0; i < 12; i++) {
                int p = tid + (i << 7);
                int k = p >> 9, row = (p >> 3) & 63, f4 = p & 7;
                uint32_t dst = smem_u32(&buf[cur ^ 1][k][row][f4 << 2]);
                const float* src = u + ((size_t)(b0 + row) * 3 + k) * TLEN + tt + (f4 << 2);
                CP_ASYNC16(dst, src);
            }
            CP_COMMIT();
            asm volatile("cp.async.wait_group 1;");
        } else {
            asm volatile("cp.async.wait_group 0;");
        }
        __syncthreads();

        if (tid < ROWS_PB) {
            if (emit) {
#pragma unroll
                for (int t4 = 0; t4 < 8; t4++) {
                    float4 c0 = *reinterpret_cast<float4*>(&buf[cur][0][tid][t4 << 2]);
                    float4 c1 = *reinterpret_cast<float4*>(&buf[cur][1][tid][t4 << 2]);
                    float4 c2 = *reinterpret_cast<float4*>(&buf[cur][2][tid][t4 << 2]);
                    float4 o0, o1, o2;
                    lif_step_s(c0.x, c1.x, c2.x, v0, v1, v2, o0.x, o1.x, o2.x);
                    lif_step_s(c0.y, c1.y, c2.y, v0, v1, v2, o0.y, o1.y, o2.y);
                    lif_step_s(c0.z, c1.z, c2.z, v0, v1, v2, o0.z, o1.z, o2.z);
                    lif_step_s(c0.w, c1.w, c2.w, v0, v1, v2, o0.w, o1.w, o2.w);
                    *reinterpret_cast<float4*>(&buf[cur][0][tid][t4 << 2]) = o0;
                    *reinterpret_cast<float4*>(&buf[cur][1][tid][t4 << 2]) = o1;
                    *reinterpret_cast<float4*>(&buf[cur][2][tid][t4 << 2]) = o2;
                }
            } else {
#pragma unroll
                for (int t4 = 0; t4 < 8; t4++) {
                    float4 c0 = *reinterpret_cast<float4*>(&buf[cur][0][tid][t4 << 2]);
                    float4 c1 = *reinterpret_cast<float4*>(&buf[cur][1][tid][t4 << 2]);
                    float4 c2 = *reinterpret_cast<float4*>(&buf[cur][2][tid][t4 << 2]);
                    float4 o0, o1, o2;
                    lif_step_s(c0.x, c1.x, c2.x, v0, v1, v2, o0.x, o1.x, o2.x);
                    lif_step_s(c0.y, c1.y, c2.y, v0, v1, v2, o0.y, o1.y, o2.y);
                    lif_step_s(c0.z, c1.z, c2.z, v0, v1, v2, o0.z, o1.z, o2.z);
                    lif_step_s(c0.w, c1.w, c2.w, v0, v1, v2, o0.w, o1.w, o2.w);
                }
            }
        }

        if (emit) {
            __syncthreads();     // spikes visible to all threads
            int tt = t_begin + ti * TILE;
#pragma unroll
            for (int i = 0; i < 12; i++) {
                int p = tid + (i << 7);
                int k = p >> 9, row = (p >> 3) & 63, f4 = p & 7;
                float4 o = *reinterpret_cast<float4*>(&buf[cur][k][row][f4 << 2]);
                *reinterpret_cast<float4*>(
                    s + ((size_t)(b0 + row) * 3 + k) * TLEN + tt + (f4 << 2)) = o;
            }
        }
        __syncthreads();         // buf[cur] free for re-staging
    }
}

// ---------------------------------------------------------------------------
// Launch: conv in two t-halves; scan in two 8-segment groups (256 blocks each)
// overlapped with conv's second half via event fork/join (round-7 mechanics,
// grid-safe launch sizes this time).
// ---------------------------------------------------------------------------
extern "C" void kernel_launch(void* const* d_in, const int* in_sizes, int n_in,
                              void* d_out, int out_size)
{
    const float* x   = (const float*)d_in[0];
    const float* w8  = (const float*)d_in[1];
    const float* w16 = (const float*)d_in[2];
    const float* w32 = (const float*)d_in[3];

    float* u = (float*)d_out;
    float* s = u + (size_t)BATCH * 3 * TLEN;

    static cudaStream_t s1 = nullptr;
    static cudaEvent_t ev0 = nullptr, ev1 = nullptr, evj = nullptr;
    if (s1 == nullptr) {
        cudaStreamCreateWithFlags(&s1, cudaStreamNonBlocking);
        cudaEventCreateWithFlags(&ev0, cudaEventDisableTiming);
        cudaEventCreateWithFlags(&ev1, cudaEventDisableTiming);
        cudaEventCreateWithFlags(&evj, cudaEventDisableTiming);
    }

    const int HALF_T = TLEN / 2;                      // 2048

    // conv half 0: t in [0, 2048)
    conv_kernel<<<dim3(HALF_T / 64, BATCH / 32), dim3(8, 32)>>>(
        x, w8, w16, w32, u, 0);
    cudaEventRecord(ev0, 0);

    // conv half 1: t in [2048, 4096)  (overlaps scan group 0)
    conv_kernel<<<dim3(HALF_T / 64, BATCH / 32), dim3(8, 32)>>>(
        x, w8, w16, w32, u, HALF_T);
    cudaEventRecord(ev1, 0);

    // scan group 0: segments 0..7 (outputs t < 2048; warm-up reads < 2048)
    cudaStreamWaitEvent(s1, ev0, 0);
    scan_fused<<<dim3(BATCH / ROWS_PB, NSEG / 2), 128, 0, s1>>>(u, s, 0);

    // scan group 1: segments 8..15 (needs all of u)
    cudaStreamWaitEvent(s1, ev1, 0);
    scan_fused<<<dim3(BATCH / ROWS_PB, NSEG / 2), 128, 0, s1>>>(u, s, NSEG / 2);

    cudaEventRecord(evj, s1);
    cudaStreamWaitEvent(0, evj, 0);
}

// round 11
// speedup vs baseline: 1.3545x; 1.3545x over previous
#include <cuda_runtime.h>
#include <cstdint>

#define BATCH 2048
#define TLEN  4096
#define ALPHA_C 0.95f
#define THETA_C 0.05f

// scan geometry
#define ROWS_PB 64
#define SEG     256
#define NSEG    (TLEN / SEG)        // 16
#define WU      384                 // warm-up steps (alpha^384 ~ 3e-9)
#define TILE    32
#define TSTRIDE 36                  // 144B row stride; conflict-free LDS.128

#define CP_ASYNC16(dst, src) \
    asm volatile("cp.async.cg.shared.global [%0], [%1], 16;" :: "r"(dst), "l"(src))
#define CP_COMMIT() asm volatile("cp.async.commit_group;")

__device__ __forceinline__ uint32_t smem_u32(const void* p) {
    return (uint32_t)__cvta_generic_to_shared(p);
}

// ---------------------------------------------------------------------------
// Kernel 1: causal convs — bitwise-identical math to rounds 4-10.
// ---------------------------------------------------------------------------
__global__ void __launch_bounds__(256) conv_kernel(
    const float* __restrict__ x,
    const float* __restrict__ w8,
    const float* __restrict__ w16,
    const float* __restrict__ w32,
    float* __restrict__ u)
{
    __shared__ float xs[32][97];
    __shared__ float sw8[8], sw16[16], sw32[32];

    const int tx  = threadIdx.x;
    const int ty  = threadIdx.y;
    const int tid = ty * 8 + tx;
    const int t0  = blockIdx.x * 64;
    const int b0  = blockIdx.y * 32;
    const int warp = tid >> 5;
    const int lane = tid & 31;

    if (tid < 8)       sw8[tid]       = w8[tid];
    else if (tid < 24) sw16[tid - 8]  = w16[tid - 8];
    else if (tid < 56) sw32[tid - 24] = w32[tid - 24];

    {
        const int r0 = warp << 2;
#pragma unroll
        for (int rr = 0; rr < 4; rr++) {
            const float* xrow = x + (size_t)(b0 + r0 + rr) * TLEN;
#pragma unroll
            for (int seg = 0; seg < 3; seg++) {
                int i = (seg << 5) + lane;
                int t = t0 - 32 + i;
                xs[r0 + rr][i] = (t >= 0) ? xrow[t] : 0.0f;
            }
        }
    }
    __syncthreads();

    float xw[39];
#pragma unroll
    for (int j = 0; j < 39; j++) xw[j] = xs[ty][(tx << 3) + 1 + j];

    float a8[8], a16[8], a32[8];
#pragma unroll
    for (int i = 0; i < 8; i++) { a8[i] = 0.f; a16[i] = 0.f; a32[i] = 0.f; }

#pragma unroll
    for (int j = 0; j < 32; j++) {
        float w = sw32[j];
#pragma unroll
        for (int i = 0; i < 8; i++) a32[i] = fmaf(w, xw[i + j], a32[i]);
    }
#pragma unroll
    for (int j = 0; j < 16; j++) {
        float w = sw16[j];
#pragma unroll
        for (int i = 0; i < 8; i++) a16[i] = fmaf(w, xw[16 + i + j], a16[i]);
    }
#pragma unroll
    for (int j = 0; j < 8; j++) {
        float w = sw8[j];
#pragma unroll
        for (int i = 0; i < 8; i++) a8[i] = fmaf(w, xw[24 + i + j], a8[i]);
    }

    float* ub = u + ((size_t)(b0 + ty) * 3) * TLEN + t0 + (tx << 3);
    reinterpret_cast<float4*>(ub + 0 * TLEN)[0] = make_float4(a8[0],  a8[1],  a8[2],  a8[3]);
    reinterpret_cast<float4*>(ub + 0 * TLEN)[1] = make_float4(a8[4],  a8[5],  a8[6],  a8[7]);
    reinterpret_cast<float4*>(ub + 1 * TLEN)[0] = make_float4(a16[0], a16[1], a16[2], a16[3]);
    reinterpret_cast<float4*>(ub + 1 * TLEN)[1] = make_float4(a16[4], a16[5], a16[6], a16[7]);
    reinterpret_cast<float4*>(ub + 2 * TLEN)[0] = make_float4(a32[0], a32[1], a32[2], a32[3]);
    reinterpret_cast<float4*>(ub + 2 * TLEN)[1] = make_float4(a32[4], a32[5], a32[6], a32[7]);
}

// ---------------------------------------------------------------------------
// LIF + WTA step — decision logic IDENTICAL to validated rounds 1-10.
// ---------------------------------------------------------------------------
__device__ __forceinline__ void lif_step_s(float u0, float u1, float u2,
                                           float& v0, float& v1, float& v2,
                                           float& s0, float& s1, float& s2)
{
    float w0 = fmaf(ALPHA_C, v0, u0);
    float w1 = fmaf(ALPHA_C, v1, u1);
    float w2 = fmaf(ALPHA_C, v2, u2);
    float m0 = w0 - THETA_C;
    float m1 = w1 - THETA_C;
    float m2 = w2 - THETA_C;
    float best = fmaxf(m0, fmaxf(m1, m2));
    bool fire = (best >= 0.0f);
    bool t0 = (m0 == best);
    bool t1 = (m1 == best);
    bool e0 = fire && t0;
    bool e1 = fire && t1 && !t0;
    bool e2 = fire && !t0 && !t1;
    s0 = e0 ? 1.0f : 0.0f;
    s1 = e1 ? 1.0f : 0.0f;
    s2 = e2 ? 1.0f : 0.0f;
    v0 = e0 ? m0 : w0;
    v1 = e1 ? m1 : w1;
    v2 = e2 ? m2 : w2;
}

// ---------------------------------------------------------------------------
// Kernel 2: fused LIF scan — single launch, ALL 16 segments (512 blocks).
// 128 threads: 0-63 compute one row each; all 128 stage + store out.
// ---------------------------------------------------------------------------
__global__ void __launch_bounds__(128, 4) scan_fused(
    const float* __restrict__ u, float* __restrict__ s)
{
    __shared__ float buf[2][3][ROWS_PB][TSTRIDE];

    const int tid = threadIdx.x;              // 0..127
    const int b0  = blockIdx.x * ROWS_PB;
    const int seg = blockIdx.y;

    const int t_out0   = seg * SEG;
    const int t_begin  = (t_out0 >= WU) ? (t_out0 - WU) : 0;
    const int ntiles   = (t_out0 + SEG - t_begin) / TILE;
    const int wu_tiles = (t_out0 - t_begin) / TILE;

    // staging: 3*64*8 = 1536 16B tasks per tile, 12 per thread
    // p = tid + 128*i -> k = p>>9, row = (p>>3)&63, f4 = p&7
    {
        int tt = t_begin;
#pragma unroll
        for (int i = 0; i < 12; i++) {
            int p = tid + (i << 7);
            int k = p >> 9, row = (p >> 3) & 63, f4 = p & 7;
            uint32_t dst = smem_u32(&buf[0][k][row][f4 << 2]);
            const float* src = u + ((size_t)(b0 + row) * 3 + k) * TLEN + tt + (f4 << 2);
            CP_ASYNC16(dst, src);
        }
        CP_COMMIT();
    }

    float v0 = 0.f, v1 = 0.f, v2 = 0.f;

#pragma unroll 1
    for (int ti = 0; ti < ntiles; ti++) {
        const int cur = ti & 1;
        const bool has_next = (ti + 1 < ntiles);
        const bool emit = (ti >= wu_tiles);

        if (has_next) {
            int tt = t_begin + (ti + 1) * TILE;
#pragma unroll
            for (int i = 0; i < 12; i++) {
                int p = tid + (i << 7);
                int k = p >> 9, row = (p >> 3) & 63, f4 = p & 7;
                uint32_t dst = smem_u32(&buf[cur ^ 1][k][row][f4 << 2]);
                const float* src = u + ((size_t)(b0 + row) * 3 + k) * TLEN + tt + (f4 << 2);
                CP_ASYNC16(dst, src);
            }
            CP_COMMIT();
            asm volatile("cp.async.wait_group 1;");
        } else {
            asm volatile("cp.async.wait_group 0;");
        }
        __syncthreads();

        if (tid < ROWS_PB) {
            if (emit) {
#pragma unroll
                for (int t4 = 0; t4 < 8; t4++) {
                    float4 c0 = *reinterpret_cast<float4*>(&buf[cur][0][tid][t4 << 2]);
                    float4 c1 = *reinterpret_cast<float4*>(&buf[cur][1][tid][t4 << 2]);
                    float4 c2 = *reinterpret_cast<float4*>(&buf[cur][2][tid][t4 << 2]);
                    float4 o0, o1, o2;
                    lif_step_s(c0.x, c1.x, c2.x, v0, v1, v2, o0.x, o1.x, o2.x);
                    lif_step_s(c0.y, c1.y, c2.y, v0, v1, v2, o0.y, o1.y, o2.y);
                    lif_step_s(c0.z, c1.z, c2.z, v0, v1, v2, o0.z, o1.z, o2.z);
                    lif_step_s(c0.w, c1.w, c2.w, v0, v1, v2, o0.w, o1.w, o2.w);
                    *reinterpret_cast<float4*>(&buf[cur][0][tid][t4 << 2]) = o0;
                    *reinterpret_cast<float4*>(&buf[cur][1][tid][t4 << 2]) = o1;
                    *reinterpret_cast<float4*>(&buf[cur][2][tid][t4 << 2]) = o2;
                }
            } else {
#pragma unroll
                for (int t4 = 0; t4 < 8; t4++) {
                    float4 c0 = *reinterpret_cast<float4*>(&buf[cur][0][tid][t4 << 2]);
                    float4 c1 = *reinterpret_cast<float4*>(&buf[cur][1][tid][t4 << 2]);
                    float4 c2 = *reinterpret_cast<float4*>(&buf[cur][2][tid][t4 << 2]);
                    float4 o0, o1, o2;
                    lif_step_s(c0.x, c1.x, c2.x, v0, v1, v2, o0.x, o1.x, o2.x);
                    lif_step_s(c0.y, c1.y, c2.y, v0, v1, v2, o0.y, o1.y, o2.y);
                    lif_step_s(c0.z, c1.z, c2.z, v0, v1, v2, o0.z, o1.z, o2.z);
                    lif_step_s(c0.w, c1.w, c2.w, v0, v1, v2, o0.w, o1.w, o2.w);
                }
            }
        }

        if (emit) {
            __syncthreads();     // spikes visible to all threads
            int tt = t_begin + ti * TILE;
#pragma unroll
            for (int i = 0; i < 12; i++) {
                int p = tid + (i << 7);
                int k = p >> 9, row = (p >> 3) & 63, f4 = p & 7;
                float4 o = *reinterpret_cast<float4*>(&buf[cur][k][row][f4 << 2]);
                *reinterpret_cast<float4*>(
                    s + ((size_t)(b0 + row) * 3 + k) * TLEN + tt + (f4 << 2)) = o;
            }
        }
        __syncthreads();         // buf[cur] free for re-staging
    }
}

// ---------------------------------------------------------------------------
extern "C" void kernel_launch(void* const* d_in, const int* in_sizes, int n_in,
                              void* d_out, int out_size)
{
    const float* x   = (const float*)d_in[0];
    const float* w8  = (const float*)d_in[1];
    const float* w16 = (const float*)d_in[2];
    const float* w32 = (const float*)d_in[3];

    float* u = (float*)d_out;
    float* s = u + (size_t)BATCH * 3 * TLEN;

    conv_kernel<<<dim3(TLEN / 64, BATCH / 32), dim3(8, 32)>>>(x, w8, w16, w32, u);
    scan_fused<<<dim3(BATCH / ROWS_PB, NSEG), 128>>>(u, s);
}

// round 12
// speedup vs baseline: 1.4394x; 1.0627x over previous
#include <cuda_runtime.h>
#include <cstdint>

#define BATCH 2048
#define TLEN  4096
#define ALPHA_C 0.95f
#define THETA_C 0.05f

// scan geometry
#define ROWS_PB 32                  // batch rows per block
#define SEG     512                 // output timesteps per block
#define NSEG    (TLEN / SEG)        // 8
#define WU      384                 // warm-up steps (alpha^384 ~ 3e-9)
#define TILE    32
#define TSTRIDE 36                  // 144B row stride; conflict-free LDS.128

#define CP_ASYNC16(dst, src) \
    asm volatile("cp.async.cg.shared.global [%0], [%1], 16;" :: "r"(dst), "l"(src))
#define CP_COMMIT() asm volatile("cp.async.commit_group;")

__device__ __forceinline__ uint32_t smem_u32(const void* p) {
    return (uint32_t)__cvta_generic_to_shared(p);
}

// ---------------------------------------------------------------------------
// Kernel 1: causal convs — bitwise-identical math to rounds 4-11.
// ---------------------------------------------------------------------------
__global__ void __launch_bounds__(256) conv_kernel(
    const float* __restrict__ x,
    const float* __restrict__ w8,
    const float* __restrict__ w16,
    const float* __restrict__ w32,
    float* __restrict__ u)
{
    __shared__ float xs[32][97];
    __shared__ float sw8[8], sw16[16], sw32[32];

    const int tx  = threadIdx.x;
    const int ty  = threadIdx.y;
    const int tid = ty * 8 + tx;
    const int t0  = blockIdx.x * 64;
    const int b0  = blockIdx.y * 32;
    const int warp = tid >> 5;
    const int lane = tid & 31;

    if (tid < 8)       sw8[tid]       = w8[tid];
    else if (tid < 24) sw16[tid - 8]  = w16[tid - 8];
    else if (tid < 56) sw32[tid - 24] = w32[tid - 24];

    {
        const int r0 = warp << 2;
#pragma unroll
        for (int rr = 0; rr < 4; rr++) {
            const float* xrow = x + (size_t)(b0 + r0 + rr) * TLEN;
#pragma unroll
            for (int seg = 0; seg < 3; seg++) {
                int i = (seg << 5) + lane;
                int t = t0 - 32 + i;
                xs[r0 + rr][i] = (t >= 0) ? xrow[t] : 0.0f;
            }
        }
    }
    __syncthreads();

    float xw[39];
#pragma unroll
    for (int j = 0; j < 39; j++) xw[j] = xs[ty][(tx << 3) + 1 + j];

    float a8[8], a16[8], a32[8];
#pragma unroll
    for (int i = 0; i < 8; i++) { a8[i] = 0.f; a16[i] = 0.f; a32[i] = 0.f; }

#pragma unroll
    for (int j = 0; j < 32; j++) {
        float w = sw32[j];
#pragma unroll
        for (int i = 0; i < 8; i++) a32[i] = fmaf(w, xw[i + j], a32[i]);
    }
#pragma unroll
    for (int j = 0; j < 16; j++) {
        float w = sw16[j];
#pragma unroll
        for (int i = 0; i < 8; i++) a16[i] = fmaf(w, xw[16 + i + j], a16[i]);
    }
#pragma unroll
    for (int j = 0; j < 8; j++) {
        float w = sw8[j];
#pragma unroll
        for (int i = 0; i < 8; i++) a8[i] = fmaf(w, xw[24 + i + j], a8[i]);
    }

    float* ub = u + ((size_t)(b0 + ty) * 3) * TLEN + t0 + (tx << 3);
    reinterpret_cast<float4*>(ub + 0 * TLEN)[0] = make_float4(a8[0],  a8[1],  a8[2],  a8[3]);
    reinterpret_cast<float4*>(ub + 0 * TLEN)[1] = make_float4(a8[4],  a8[5],  a8[6],  a8[7]);
    reinterpret_cast<float4*>(ub + 1 * TLEN)[0] = make_float4(a16[0], a16[1], a16[2], a16[3]);
    reinterpret_cast<float4*>(ub + 1 * TLEN)[1] = make_float4(a16[4], a16[5], a16[6], a16[7]);
    reinterpret_cast<float4*>(ub + 2 * TLEN)[0] = make_float4(a32[0], a32[1], a32[2], a32[3]);
    reinterpret_cast<float4*>(ub + 2 * TLEN)[1] = make_float4(a32[4], a32[5], a32[6], a32[7]);
}

// ---------------------------------------------------------------------------
// LIF + WTA step — decision logic IDENTICAL to validated rounds 1-11.
// ---------------------------------------------------------------------------
__device__ __forceinline__ void lif_step_s(float u0, float u1, float u2,
                                           float& v0, float& v1, float& v2,
                                           float& s0, float& s1, float& s2)
{
    float w0 = fmaf(ALPHA_C, v0, u0);
    float w1 = fmaf(ALPHA_C, v1, u1);
    float w2 = fmaf(ALPHA_C, v2, u2);
    float m0 = w0 - THETA_C;
    float m1 = w1 - THETA_C;
    float m2 = w2 - THETA_C;
    float best = fmaxf(m0, fmaxf(m1, m2));
    bool fire = (best >= 0.0f);
    bool t0 = (m0 == best);
    bool t1 = (m1 == best);
    bool e0 = fire && t0;
    bool e1 = fire && t1 && !t0;
    bool e2 = fire && !t0 && !t1;
    s0 = e0 ? 1.0f : 0.0f;
    s1 = e1 ? 1.0f : 0.0f;
    s2 = e2 ? 1.0f : 0.0f;
    v0 = e0 ? m0 : w0;
    v1 = e1 ? m1 : w1;
    v2 = e2 ? m2 : w2;
}

// ---------------------------------------------------------------------------
// Kernel 2: fused LIF scan. Block = 32 rows x one 512-t segment; 128 threads:
// tid<32 compute one row each, all 128 stage (cp.async) + store out.
// Grid (64, 8) = 512 blocks; read amplification 1.75x.
// ---------------------------------------------------------------------------
__global__ void __launch_bounds__(128, 4) scan_fused(
    const float* __restrict__ u, float* __restrict__ s)
{
    __shared__ float buf[2][3][ROWS_PB][TSTRIDE];   // 27.6 KB

    const int tid = threadIdx.x;              // 0..127
    const int b0  = blockIdx.x * ROWS_PB;
    const int seg = blockIdx.y;

    const int t_out0   = seg * SEG;
    const int t_begin  = (t_out0 >= WU) ? (t_out0 - WU) : 0;
    const int ntiles   = (t_out0 + SEG - t_begin) / TILE;   // 16 or 28
    const int wu_tiles = (t_out0 - t_begin) / TILE;         // 0 or 12

    // staging: 3*32*8 = 768 16B tasks per tile, 6 per thread
    // p = tid + 128*i -> k = p>>8, row = (p>>3)&31, f4 = p&7
    {
        int tt = t_begin;
#pragma unroll
        for (int i = 0; i < 6; i++) {
            int p = tid + (i << 7);
            int k = p >> 8, row = (p >> 3) & 31, f4 = p & 7;
            uint32_t dst = smem_u32(&buf[0][k][row][f4 << 2]);
            const float* src = u + ((size_t)(b0 + row) * 3 + k) * TLEN + tt + (f4 << 2);
            CP_ASYNC16(dst, src);
        }
        CP_COMMIT();
    }

    float v0 = 0.f, v1 = 0.f, v2 = 0.f;

#pragma unroll 1
    for (int ti = 0; ti < ntiles; ti++) {
        const int cur = ti & 1;
        const bool has_next = (ti + 1 < ntiles);
        const bool emit = (ti >= wu_tiles);

        if (has_next) {
            int tt = t_begin + (ti + 1) * TILE;
#pragma unroll
            for (int i = 0; i < 6; i++) {
                int p = tid + (i << 7);
                int k = p >> 8, row = (p >> 3) & 31, f4 = p & 7;
                uint32_t dst = smem_u32(&buf[cur ^ 1][k][row][f4 << 2]);
                const float* src = u + ((size_t)(b0 + row) * 3 + k) * TLEN + tt + (f4 << 2);
                CP_ASYNC16(dst, src);
            }
            CP_COMMIT();
            asm volatile("cp.async.wait_group 1;");
        } else {
            asm volatile("cp.async.wait_group 0;");
        }
        __syncthreads();

        if (tid < ROWS_PB) {
            if (emit) {
#pragma unroll
                for (int t4 = 0; t4 < 8; t4++) {
                    float4 c0 = *reinterpret_cast<float4*>(&buf[cur][0][tid][t4 << 2]);
                    float4 c1 = *reinterpret_cast<float4*>(&buf[cur][1][tid][t4 << 2]);
                    float4 c2 = *reinterpret_cast<float4*>(&buf[cur][2][tid][t4 << 2]);
                    float4 o0, o1, o2;
                    lif_step_s(c0.x, c1.x, c2.x, v0, v1, v2, o0.x, o1.x, o2.x);
                    lif_step_s(c0.y, c1.y, c2.y, v0, v1, v2, o0.y, o1.y, o2.y);
                    lif_step_s(c0.z, c1.z, c2.z, v0, v1, v2, o0.z, o1.z, o2.z);
                    lif_step_s(c0.w, c1.w, c2.w, v0, v1, v2, o0.w, o1.w, o2.w);
                    *reinterpret_cast<float4*>(&buf[cur][0][tid][t4 << 2]) = o0;
                    *reinterpret_cast<float4*>(&buf[cur][1][tid][t4 << 2]) = o1;
                    *reinterpret_cast<float4*>(&buf[cur][2][tid][t4 << 2]) = o2;
                }
            } else {
#pragma unroll
                for (int t4 = 0; t4 < 8; t4++) {
                    float4 c0 = *reinterpret_cast<float4*>(&buf[cur][0][tid][t4 << 2]);
                    float4 c1 = *reinterpret_cast<float4*>(&buf[cur][1][tid][t4 << 2]);
                    float4 c2 = *reinterpret_cast<float4*>(&buf[cur][2][tid][t4 << 2]);
                    float4 o0, o1, o2;
                    lif_step_s(c0.x, c1.x, c2.x, v0, v1, v2, o0.x, o1.x, o2.x);
                    lif_step_s(c0.y, c1.y, c2.y, v0, v1, v2, o0.y, o1.y, o2.y);
                    lif_step_s(c0.z, c1.z, c2.z, v0, v1, v2, o0.z, o1.z, o2.z);
                    lif_step_s(c0.w, c1.w, c2.w, v0, v1, v2, o0.w, o1.w, o2.w);
                }
            }
        }

        if (emit) {
            __syncthreads();     // spikes visible to all threads
            int tt = t_begin + ti * TILE;
#pragma unroll
            for (int i = 0; i < 6; i++) {
                int p = tid + (i << 7);
                int k = p >> 8, row = (p >> 3) & 31, f4 = p & 7;
                float4 o = *reinterpret_cast<float4*>(&buf[cur][k][row][f4 << 2]);
                *reinterpret_cast<float4*>(
                    s + ((size_t)(b0 + row) * 3 + k) * TLEN + tt + (f4 << 2)) = o;
            }
        }
        __syncthreads();         // buf[cur] free for re-staging
    }
}

// ---------------------------------------------------------------------------
extern "C" void kernel_launch(void* const* d_in, const int* in_sizes, int n_in,
                              void* d_out, int out_size)
{
    const float* x   = (const float*)d_in[0];
    const float* w8  = (const float*)d_in[1];
    const float* w16 = (const float*)d_in[2];
    const float* w32 = (const float*)d_in[3];

    float* u = (float*)d_out;
    float* s = u + (size_t)BATCH * 3 * TLEN;

    conv_kernel<<<dim3(TLEN / 64, BATCH / 32), dim3(8, 32)>>>(x, w8, w16, w32, u);
    scan_fused<<<dim3(BATCH / ROWS_PB, NSEG), 128>>>(u, s);
}